// round 13
// baseline (speedup 1.0000x reference)
#include <cuda_runtime.h>
#include <cuda_fp16.h>

#define BOHR        0.52917721067f
#define A_MUTUAL    0.39f
#define MAX_NODES   262144

// Scratch (no allocations allowed).
__device__ float4 g_pack[MAX_NODES];   // {mu.x, mu.y, mu.z, q=rsqrt(pol_bohr)}
__device__ __half g_q16[MAX_NODES];    // dense fp16 q (L1-friendly src gather)
__device__ float4 g_acc[MAX_NODES];    // accumulator, pre-init to mu*q^2 (diag term)

// 1 node/thread (fastest measured). Pre-seeds the diagonal term.
__global__ void pack_kernel(const float* __restrict__ pol,
                            const float* __restrict__ mu,
                            int n_nodes)
{
    int i = blockIdx.x * blockDim.x + threadIdx.x;
    if (i >= n_nodes) return;
    const float inv_bohr3 = 1.0f / (BOHR * BOHR * BOHR);
    float q  = rsqrtf(pol[i] * inv_bohr3);
    float q2 = q * q;                       // == 1/pol_bohr
    float mx = mu[3 * i + 0];
    float my = mu[3 * i + 1];
    float mz = mu[3 * i + 2];
    g_pack[i] = make_float4(mx, my, mz, q);
    g_q16[i]  = __float2half_rn(q);
    g_acc[i]  = make_float4(mx * q2, my * q2, mz * q2, 0.f);  // diagonal term
}

// float4 gather that bypasses L1 allocation (3.2MB ws can never be L1-resident;
// don't let it evict the q lines).
__device__ __forceinline__ float4 ldg_na(const float4* p)
{
    float4 v;
    asm("ld.global.nc.L1::no_allocate.v4.f32 {%0,%1,%2,%3}, [%4];"
        : "=f"(v.x), "=f"(v.y), "=f"(v.z), "=f"(v.w) : "l"(p));
    return v;
}

// Proven edge body; gathers issued back-to-back first; block=1024 probe.
__global__ void __launch_bounds__(1024)
edge_kernel(const int*   __restrict__ edge_src,
            const int*   __restrict__ edge_dst,
            const float* __restrict__ distances,
            const float* __restrict__ vec,
            int n_edges)
{
    const float inv_bohr = 1.0f / BOHR;

    int e = blockIdx.x * blockDim.x + threadIdx.x;
    if (e >= n_edges) return;

    int src = __ldcs(edge_src + e);
    int dst = __ldcs(edge_dst + e);

    // Issue both random gathers immediately (two independent chains in flight).
    float4 pd = ldg_na(&g_pack[dst]);
    float  qs = __half2float(g_q16[src]);

    float rij = __ldcs(distances + e) * inv_bohr;
    float vx  = __ldcs(vec + 3 * e + 0) * inv_bohr;
    float vy  = __ldcs(vec + 3 * e + 1) * inv_bohr;
    float vz  = __ldcs(vec + 3 * e + 2) * inv_bohr;

    float inv_sqrt_alpha = qs * pd.w;
    float rij2 = rij * rij;
    float rij3 = rij2 * rij;
    float au3  = A_MUTUAL * rij3 * inv_sqrt_alpha;

    float eexp = __expf(-au3);
    float lam3 = 1.0f - eexp;
    float lam5 = 1.0f - (1.0f + au3) * eexp;

    float inv_r3 = 1.0f / rij3;
    float inv_r5 = inv_r3 / rij2;

    float dot = vx * pd.x + vy * pd.y + vz * pd.z;

    float c3 = lam3 * inv_r3;
    float c5 = 3.0f * lam5 * inv_r5 * dot;

    float cx = c3 * pd.x - c5 * vx;
    float cy = c3 * pd.y - c5 * vy;
    float cz = c3 * pd.z - c5 * vz;

    float4* dstp = &g_acc[src];
    asm volatile("red.global.add.v4.f32 [%0], {%1, %2, %3, %4};"
                 :: "l"(dstp), "f"(cx), "f"(cy), "f"(cz), "f"(0.0f)
                 : "memory");
}

// final: pure layout copy float4 -> packed float3. 2 nodes/thread.
__global__ void final_kernel(float* __restrict__ out, int n_nodes)
{
    int t  = blockIdx.x * blockDim.x + threadIdx.x;
    int i0 = 2 * t;
    if (i0 >= n_nodes) return;

    if (i0 + 1 < n_nodes) {
        float4 a0 = g_acc[i0 + 0];
        float4 a1 = g_acc[i0 + 1];
        float2* o = (float2*)(out + 3 * i0);
        o[0] = make_float2(a0.x, a0.y);
        o[1] = make_float2(a0.z, a1.x);
        o[2] = make_float2(a1.y, a1.z);
    } else {
        float4 a = g_acc[i0];
        out[3 * i0 + 0] = a.x;
        out[3 * i0 + 1] = a.y;
        out[3 * i0 + 2] = a.z;
    }
}

extern "C" void kernel_launch(void* const* d_in, const int* in_sizes, int n_in,
                              void* d_out, int out_size)
{
    const int*   edge_src = (const int*)  d_in[1];
    const int*   edge_dst = (const int*)  d_in[2];
    const float* dists    = (const float*)d_in[3];
    const float* vec      = (const float*)d_in[4];
    const float* pol      = (const float*)d_in[5];
    const float* mu       = (const float*)d_in[6];
    float*       out      = (float*)d_out;

    int n_edges = in_sizes[3];
    int n_nodes = in_sizes[5];

    const int tb  = 256;
    const int etb = 1024;
    pack_kernel<<<(n_nodes + tb - 1) / tb, tb>>>(pol, mu, n_nodes);
    edge_kernel<<<(n_edges + etb - 1) / etb, etb>>>(edge_src, edge_dst, dists, vec, n_edges);
    final_kernel<<<((n_nodes + 1) / 2 + tb - 1) / tb, tb>>>(out, n_nodes);
}

// round 14
// speedup vs baseline: 1.0320x; 1.0320x over previous
#include <cuda_runtime.h>
#include <cuda_fp16.h>

#define BOHR        0.52917721067f
#define A_MUTUAL    0.39f
#define MAX_NODES   262144

// Scratch (no allocations allowed).
__device__ float4 g_pack[MAX_NODES];   // {mu.x, mu.y, mu.z, q=rsqrt(pol_bohr)}
__device__ __half g_q16[MAX_NODES];    // dense fp16 q (L1-friendly src gather)
__device__ float4 g_acc[MAX_NODES];    // accumulator, pre-init to mu*q^2 (diag term)

// 1 node/thread (fastest measured). Pre-seeds the diagonal term.
__global__ void pack_kernel(const float* __restrict__ pol,
                            const float* __restrict__ mu,
                            int n_nodes)
{
    int i = blockIdx.x * blockDim.x + threadIdx.x;
    if (i >= n_nodes) return;
    const float inv_bohr3 = 1.0f / (BOHR * BOHR * BOHR);
    float q  = rsqrtf(pol[i] * inv_bohr3);
    float q2 = q * q;                       // == 1/pol_bohr
    float mx = mu[3 * i + 0];
    float my = mu[3 * i + 1];
    float mz = mu[3 * i + 2];
    g_pack[i] = make_float4(mx, my, mz, q);
    g_q16[i]  = __float2half_rn(q);
    g_acc[i]  = make_float4(mx * q2, my * q2, mz * q2, 0.f);  // diagonal term
}

// float4 gather that bypasses L1 allocation (3.2MB ws can never be L1-resident;
// don't let it evict the q lines).
__device__ __forceinline__ float4 ldg_na(const float4* p)
{
    float4 v;
    asm("ld.global.nc.L1::no_allocate.v4.f32 {%0,%1,%2,%3}, [%4];"
        : "=f"(v.x), "=f"(v.y), "=f"(v.z), "=f"(v.w) : "l"(p));
    return v;
}

// Proven edge body; gathers issued back-to-back first; block=512 (measured optimum).
__global__ void __launch_bounds__(512)
edge_kernel(const int*   __restrict__ edge_src,
            const int*   __restrict__ edge_dst,
            const float* __restrict__ distances,
            const float* __restrict__ vec,
            int n_edges)
{
    const float inv_bohr = 1.0f / BOHR;

    int e = blockIdx.x * blockDim.x + threadIdx.x;
    if (e >= n_edges) return;

    int src = __ldcs(edge_src + e);
    int dst = __ldcs(edge_dst + e);

    // Issue both random gathers immediately (two independent chains in flight).
    float4 pd = ldg_na(&g_pack[dst]);
    float  qs = __half2float(g_q16[src]);

    float rij = __ldcs(distances + e) * inv_bohr;
    float vx  = __ldcs(vec + 3 * e + 0) * inv_bohr;
    float vy  = __ldcs(vec + 3 * e + 1) * inv_bohr;
    float vz  = __ldcs(vec + 3 * e + 2) * inv_bohr;

    float inv_sqrt_alpha = qs * pd.w;
    float rij2 = rij * rij;
    float rij3 = rij2 * rij;
    float au3  = A_MUTUAL * rij3 * inv_sqrt_alpha;

    float eexp = __expf(-au3);
    float lam3 = 1.0f - eexp;
    float lam5 = 1.0f - (1.0f + au3) * eexp;

    float inv_r3 = 1.0f / rij3;
    float inv_r5 = inv_r3 / rij2;

    float dot = vx * pd.x + vy * pd.y + vz * pd.z;

    float c3 = lam3 * inv_r3;
    float c5 = 3.0f * lam5 * inv_r5 * dot;

    float cx = c3 * pd.x - c5 * vx;
    float cy = c3 * pd.y - c5 * vy;
    float cz = c3 * pd.z - c5 * vz;

    float4* dstp = &g_acc[src];
    asm volatile("red.global.add.v4.f32 [%0], {%1, %2, %3, %4};"
                 :: "l"(dstp), "f"(cx), "f"(cy), "f"(cz), "f"(0.0f)
                 : "memory");
}

// final: pure layout copy float4 -> packed float3. 2 nodes/thread.
__global__ void final_kernel(float* __restrict__ out, int n_nodes)
{
    int t  = blockIdx.x * blockDim.x + threadIdx.x;
    int i0 = 2 * t;
    if (i0 >= n_nodes) return;

    if (i0 + 1 < n_nodes) {
        float4 a0 = g_acc[i0 + 0];
        float4 a1 = g_acc[i0 + 1];
        float2* o = (float2*)(out + 3 * i0);
        o[0] = make_float2(a0.x, a0.y);
        o[1] = make_float2(a0.z, a1.x);
        o[2] = make_float2(a1.y, a1.z);
    } else {
        float4 a = g_acc[i0];
        out[3 * i0 + 0] = a.x;
        out[3 * i0 + 1] = a.y;
        out[3 * i0 + 2] = a.z;
    }
}

extern "C" void kernel_launch(void* const* d_in, const int* in_sizes, int n_in,
                              void* d_out, int out_size)
{
    const int*   edge_src = (const int*)  d_in[1];
    const int*   edge_dst = (const int*)  d_in[2];
    const float* dists    = (const float*)d_in[3];
    const float* vec      = (const float*)d_in[4];
    const float* pol      = (const float*)d_in[5];
    const float* mu       = (const float*)d_in[6];
    float*       out      = (float*)d_out;

    int n_edges = in_sizes[3];
    int n_nodes = in_sizes[5];

    const int tb  = 256;
    const int etb = 512;
    pack_kernel<<<(n_nodes + tb - 1) / tb, tb>>>(pol, mu, n_nodes);
    edge_kernel<<<(n_edges + etb - 1) / etb, etb>>>(edge_src, edge_dst, dists, vec, n_edges);
    final_kernel<<<((n_nodes + 1) / 2 + tb - 1) / tb, tb>>>(out, n_nodes);
}

// round 15
// speedup vs baseline: 1.0556x; 1.0229x over previous
#include <cuda_runtime.h>
#include <cuda_fp16.h>

#define BOHR        0.52917721067f
#define A_MUTUAL    0.39f
#define MAX_NODES   262144

// Scratch (no allocations allowed).
__device__ float4 g_pack[MAX_NODES];   // {mu.x, mu.y, mu.z, q=rsqrt(pol_bohr)}
__device__ __half g_q16[MAX_NODES];    // dense fp16 q (L1-friendly src gather)
__device__ float4 g_acc[MAX_NODES];    // accumulator, pre-init to mu*q^2 (diag term)

// 1 node/thread (fastest measured). Pre-seeds the diagonal term.
__global__ void pack_kernel(const float* __restrict__ pol,
                            const float* __restrict__ mu,
                            int n_nodes)
{
    int i = blockIdx.x * blockDim.x + threadIdx.x;
    if (i >= n_nodes) return;
    const float inv_bohr3 = 1.0f / (BOHR * BOHR * BOHR);
    float q  = rsqrtf(pol[i] * inv_bohr3);
    float q2 = q * q;                       // == 1/pol_bohr
    float mx = mu[3 * i + 0];
    float my = mu[3 * i + 1];
    float mz = mu[3 * i + 2];
    g_pack[i] = make_float4(mx, my, mz, q);
    g_q16[i]  = __float2half_rn(q);
    g_acc[i]  = make_float4(mx * q2, my * q2, mz * q2, 0.f);  // diagonal term
}

// float4 gather that bypasses L1 allocation (3.2MB ws can never be L1-resident;
// don't let it evict the q lines).
__device__ __forceinline__ float4 ldg_na(const float4* p)
{
    float4 v;
    asm("ld.global.nc.L1::no_allocate.v4.f32 {%0,%1,%2,%3}, [%4];"
        : "=f"(v.x), "=f"(v.y), "=f"(v.z), "=f"(v.w) : "l"(p));
    return v;
}

// Proven edge body; gathers issued back-to-back first; block=512 (measured optimum).
__global__ void __launch_bounds__(512)
edge_kernel(const int*   __restrict__ edge_src,
            const int*   __restrict__ edge_dst,
            const float* __restrict__ distances,
            const float* __restrict__ vec,
            int n_edges)
{
    const float inv_bohr = 1.0f / BOHR;

    int e = blockIdx.x * blockDim.x + threadIdx.x;
    if (e >= n_edges) return;

    int src = __ldcs(edge_src + e);
    int dst = __ldcs(edge_dst + e);

    // Issue both random gathers immediately (two independent chains in flight).
    float4 pd = ldg_na(&g_pack[dst]);
    float  qs = __half2float(g_q16[src]);

    float rij = __ldcs(distances + e) * inv_bohr;
    float vx  = __ldcs(vec + 3 * e + 0) * inv_bohr;
    float vy  = __ldcs(vec + 3 * e + 1) * inv_bohr;
    float vz  = __ldcs(vec + 3 * e + 2) * inv_bohr;

    float inv_sqrt_alpha = qs * pd.w;
    float rij2 = rij * rij;
    float rij3 = rij2 * rij;
    float au3  = A_MUTUAL * rij3 * inv_sqrt_alpha;

    float eexp = __expf(-au3);
    float lam3 = 1.0f - eexp;
    float lam5 = 1.0f - (1.0f + au3) * eexp;

    float inv_r3 = 1.0f / rij3;
    float inv_r5 = inv_r3 / rij2;

    float dot = vx * pd.x + vy * pd.y + vz * pd.z;

    float c3 = lam3 * inv_r3;
    float c5 = 3.0f * lam5 * inv_r5 * dot;

    float cx = c3 * pd.x - c5 * vx;
    float cy = c3 * pd.y - c5 * vy;
    float cz = c3 * pd.z - c5 * vz;

    float4* dstp = &g_acc[src];
    asm volatile("red.global.add.v4.f32 [%0], {%1, %2, %3, %4};"
                 :: "l"(dstp), "f"(cx), "f"(cy), "f"(cz), "f"(0.0f)
                 : "memory");
}

// final: pure layout copy float4 -> packed float3. 2 nodes/thread.
__global__ void final_kernel(float* __restrict__ out, int n_nodes)
{
    int t  = blockIdx.x * blockDim.x + threadIdx.x;
    int i0 = 2 * t;
    if (i0 >= n_nodes) return;

    if (i0 + 1 < n_nodes) {
        float4 a0 = g_acc[i0 + 0];
        float4 a1 = g_acc[i0 + 1];
        float2* o = (float2*)(out + 3 * i0);
        o[0] = make_float2(a0.x, a0.y);
        o[1] = make_float2(a0.z, a1.x);
        o[2] = make_float2(a1.y, a1.z);
    } else {
        float4 a = g_acc[i0];
        out[3 * i0 + 0] = a.x;
        out[3 * i0 + 1] = a.y;
        out[3 * i0 + 2] = a.z;
    }
}

extern "C" void kernel_launch(void* const* d_in, const int* in_sizes, int n_in,
                              void* d_out, int out_size)
{
    const int*   edge_src = (const int*)  d_in[1];
    const int*   edge_dst = (const int*)  d_in[2];
    const float* dists    = (const float*)d_in[3];
    const float* vec      = (const float*)d_in[4];
    const float* pol      = (const float*)d_in[5];
    const float* mu       = (const float*)d_in[6];
    float*       out      = (float*)d_out;

    int n_edges = in_sizes[3];
    int n_nodes = in_sizes[5];

    const int tb  = 256;
    const int etb = 512;
    pack_kernel<<<(n_nodes + tb - 1) / tb, tb>>>(pol, mu, n_nodes);
    edge_kernel<<<(n_edges + etb - 1) / etb, etb>>>(edge_src, edge_dst, dists, vec, n_edges);
    final_kernel<<<((n_nodes + 1) / 2 + tb - 1) / tb, tb>>>(out, n_nodes);
}